// round 4
// baseline (speedup 1.0000x reference)
#include <cuda_runtime.h>

#define NN   16384
#define NE   262144
#define NG   16
#define CIN  128
#define CHID 256
#define CLAT 64

// ---- scratch (device globals; no allocation allowed) ----
__device__ float g_deg[NN];
__device__ float g_dinv[NN];
__device__ float g_aggx[NN * CIN];    // aggregated x (pre-transform)
__device__ float g_h[NN * CHID];      // relu hidden
__device__ float g_wT[CIN * CHID];    // gcn_w transposed  [k][h]
__device__ float g_linT[CHID * CLAT]; // lin_w transposed  [k][c]
__device__ float g_zsum[NG * CLAT];
__device__ float g_cnt[NG];
__device__ float g_gdec[NG * CIN];

// ---------------------------------------------------------
__global__ void k_init() {
    int i = blockIdx.x * blockDim.x + threadIdx.x;
    if (i < NN) g_deg[i] = 1.0f;          // self-loop
    if (i < NG * CLAT) g_zsum[i] = 0.0f;
    if (i < NG) g_cnt[i] = 0.0f;
}

__global__ void k_deg(const int* __restrict__ ei) {
    int e = blockIdx.x * blockDim.x + threadIdx.x;
    if (e < NE) atomicAdd(&g_deg[ei[NE + e]], 1.0f);
}

__global__ void k_dinv() {
    int i = blockIdx.x * blockDim.x + threadIdx.x;
    if (i < NN) g_dinv[i] = rsqrtf(g_deg[i]);
}

// self-loop term: aggx[i] = x[i] / deg[i]
__global__ void k_self(const float* __restrict__ x) {
    int idx = blockIdx.x * blockDim.x + threadIdx.x;
    if (idx < NN * CIN) g_aggx[idx] = x[idx] / g_deg[idx >> 7];
}

// edge scatter over 128 input channels (aggregate BEFORE transform)
__global__ void k_scatter(const float* __restrict__ x, const int* __restrict__ ei) {
    int e = blockIdx.x;
    int t = threadIdx.x;
    int row = ei[e];
    int col = ei[NE + e];
    float norm = g_dinv[row] * g_dinv[col];
    atomicAdd(&g_aggx[col * CIN + t], x[row * CIN + t] * norm);
}

__global__ void k_wT(const float* __restrict__ gw, const float* __restrict__ lw) {
    int idx = blockIdx.x * blockDim.x + threadIdx.x;
    if (idx < CIN * CHID) {
        int h = idx >> 7, k = idx & 127;           // gcn_w [256][128]
        g_wT[k * CHID + h] = gw[idx];
    } else if (idx < CIN * CHID + CHID * CLAT) {
        int j = idx - CIN * CHID;
        int l = j >> 8, c = j & 255;               // lin_w [64][256]
        g_linT[c * CLAT + l] = lw[j];
    }
}

// h = relu(aggx @ gcn_w^T + gcn_b)   -- 4 nodes per block
__global__ void k_gcn(const float* __restrict__ gb) {
    __shared__ float sx[4][CIN];
    int i0 = blockIdx.x * 4;
    int t = threadIdx.x;
#pragma unroll
    for (int ii = 0; ii < 2; ii++) {
        int lin = t + ii * 256;
        sx[lin >> 7][lin & 127] = g_aggx[i0 * CIN + lin];
    }
    __syncthreads();
    float b = gb[t];
    float a0 = b, a1 = b, a2 = b, a3 = b;
#pragma unroll 4
    for (int k = 0; k < CIN; k++) {
        float w = g_wT[k * CHID + t];
        a0 += sx[0][k] * w;
        a1 += sx[1][k] * w;
        a2 += sx[2][k] * w;
        a3 += sx[3][k] * w;
    }
    g_h[(i0 + 0) * CHID + t] = fmaxf(a0, 0.f);
    g_h[(i0 + 1) * CHID + t] = fmaxf(a1, 0.f);
    g_h[(i0 + 2) * CHID + t] = fmaxf(a2, 0.f);
    g_h[(i0 + 3) * CHID + t] = fmaxf(a3, 0.f);
}

// z_node = h @ lin_w^T + lin_b  (+ graph pooling accumulation)
__global__ void k_z(const int* __restrict__ batch, const float* __restrict__ lb,
                    float* __restrict__ zout) {
    __shared__ float sA[4][CHID];
    int i0 = blockIdx.x * 4;
    int t = threadIdx.x;
#pragma unroll
    for (int ii = 0; ii < 4; ii++) {
        int lin = t + ii * 256;
        sA[lin >> 8][lin & 255] = g_h[i0 * CHID + lin];
    }
    __syncthreads();
    int j = t >> 6, c = t & 63;
    float acc = lb[c];
#pragma unroll 4
    for (int k = 0; k < CHID; k++) acc += sA[j][k] * g_linT[k * CLAT + c];
    int node = i0 + j;
    zout[node * CLAT + c] = acc;
    int b = batch[node];
    atomicAdd(&g_zsum[b * CLAT + c], acc);
    if (c == 0) atomicAdd(&g_cnt[b], 1.0f);
}

// z_graph + per-graph decoded row
__global__ void k_graph(const float* __restrict__ dw, const float* __restrict__ db,
                        float* __restrict__ zg_out) {
    __shared__ float zg[CLAT];
    int g = blockIdx.x, t = threadIdx.x;
    if (t < CLAT) {
        float cn = fmaxf(g_cnt[g], 1.0f);
        float v = g_zsum[g * CLAT + t] / cn;
        zg[t] = v;
        zg_out[g * CLAT + t] = v;
    }
    __syncthreads();
    float acc = db[t];
#pragma unroll
    for (int l = 0; l < CLAT; l++) acc += zg[l] * dw[t * CLAT + l];
    g_gdec[g * CIN + t] = acc;
}

__global__ void k_xhat(const int* __restrict__ batch, float* __restrict__ xo) {
    int idx = blockIdx.x * blockDim.x + threadIdx.x;
    if (idx < NN * CIN) {
        int i = idx >> 7;
        xo[idx] = g_gdec[batch[i] * CIN + (idx & 127)];
    }
}

// a_hat = sigmoid(Z Z^T), symmetric: compute upper-tri tiles, mirror via SMEM.
// Static shared only (<=48KB): K split into 2 chunks of 32.
__global__ void __launch_bounds__(256) k_ahat(const float* __restrict__ Z,
                                              float* __restrict__ out) {
    __shared__ float sm[2 * 32 * 132];   // 33792 bytes
    float* As = sm;                      // [32][132] chunk of A^T (As[k][m])
    float* Bs = sm + 32 * 132;           // [32][132]
    const int bi = blockIdx.y, bj = blockIdx.x;
    if (bj < bi) return;
    const int tid = threadIdx.x;
    const int m0 = bi * 128, n0 = bj * 128;
    const int ty = tid >> 4, tx = tid & 15;

    float c[8][8];
#pragma unroll
    for (int a = 0; a < 8; a++)
#pragma unroll
        for (int b = 0; b < 8; b++) c[a][b] = 0.f;

#pragma unroll
    for (int kk = 0; kk < 64; kk += 32) {
        // stage 128 rows x 32 k-values for A and B (transposed into smem)
#pragma unroll
        for (int i = 0; i < 4; i++) {
            int lin = tid + i * 256;       // 0..1023
            int row = lin >> 3;            // 0..127
            int kq  = (lin & 7) * 4;       // 0,4,...,28
            float4 va = *(const float4*)(Z + (m0 + row) * 64 + kk + kq);
            As[(kq + 0) * 132 + row] = va.x;
            As[(kq + 1) * 132 + row] = va.y;
            As[(kq + 2) * 132 + row] = va.z;
            As[(kq + 3) * 132 + row] = va.w;
            float4 vb = *(const float4*)(Z + (n0 + row) * 64 + kk + kq);
            Bs[(kq + 0) * 132 + row] = vb.x;
            Bs[(kq + 1) * 132 + row] = vb.y;
            Bs[(kq + 2) * 132 + row] = vb.z;
            Bs[(kq + 3) * 132 + row] = vb.w;
        }
        __syncthreads();
#pragma unroll 8
        for (int k = 0; k < 32; k++) {
            float4 a0 = *(const float4*)(As + k * 132 + ty * 8);
            float4 a1 = *(const float4*)(As + k * 132 + ty * 8 + 4);
            float4 b0 = *(const float4*)(Bs + k * 132 + tx * 8);
            float4 b1 = *(const float4*)(Bs + k * 132 + tx * 8 + 4);
            float ar[8] = {a0.x, a0.y, a0.z, a0.w, a1.x, a1.y, a1.z, a1.w};
            float br[8] = {b0.x, b0.y, b0.z, b0.w, b1.x, b1.y, b1.z, b1.w};
#pragma unroll
            for (int ii = 0; ii < 8; ii++)
#pragma unroll
                for (int jj = 0; jj < 8; jj++) c[ii][jj] += ar[ii] * br[jj];
        }
        __syncthreads();
    }

#pragma unroll
    for (int ii = 0; ii < 8; ii++)
#pragma unroll
        for (int jj = 0; jj < 8; jj++)
            c[ii][jj] = 1.0f / (1.0f + __expf(-c[ii][jj]));

    // direct tile (rows m0.., cols n0..), coalesced float4 stores
#pragma unroll
    for (int ii = 0; ii < 8; ii++) {
        long rowoff = (long)(m0 + ty * 8 + ii) * NN + n0 + tx * 8;
        *(float4*)(out + rowoff) = make_float4(c[ii][0], c[ii][1], c[ii][2], c[ii][3]);
        *(float4*)(out + rowoff + 4) = make_float4(c[ii][4], c[ii][5], c[ii][6], c[ii][7]);
    }
    if (bj == bi) return;

    // mirror tile: transpose via SMEM in two 64-column halves
    float* st = sm;  // [64][132]
#pragma unroll
    for (int h = 0; h < 2; h++) {
        __syncthreads();
        if ((tx >> 3) == h) {
            int txl = tx & 7;  // 0..7 within half
#pragma unroll
            for (int jj = 0; jj < 8; jj++)
#pragma unroll
                for (int ii = 0; ii < 8; ii++)
                    st[(txl * 8 + jj) * 132 + ty * 8 + ii] = c[ii][jj];
        }
        __syncthreads();
#pragma unroll
        for (int p = 0; p < 32; p++) {
            int lin = p * 256 + tid;       // 0..8191
            int j = lin >> 7;              // 0..63
            int i = lin & 127;
            out[(long)(n0 + h * 64 + j) * NN + m0 + i] = st[j * 132 + i];
        }
    }
}

// ---------------------------------------------------------
extern "C" void kernel_launch(void* const* d_in, const int* in_sizes, int n_in,
                              void* d_out, int out_size) {
    const float* x     = (const float*)d_in[0];
    const int*   ei    = (const int*)d_in[1];
    const int*   batch = (const int*)d_in[2];
    const float* gw    = (const float*)d_in[3];
    const float* gb    = (const float*)d_in[4];
    const float* lw    = (const float*)d_in[5];
    const float* lb    = (const float*)d_in[6];
    const float* dw    = (const float*)d_in[7];
    const float* db    = (const float*)d_in[8];

    float* out     = (float*)d_out;
    float* z_node  = out;                       // [16384, 64]
    float* z_graph = out + NN * CLAT;           // [16, 64]
    float* x_hat   = z_graph + NG * CLAT;       // [16384, 128]
    float* a_hat   = x_hat + NN * CIN;          // [16384, 16384]

    k_init<<<64, 256>>>();
    k_deg<<<NE / 256, 256>>>(ei);
    k_dinv<<<NN / 256, 256>>>();
    k_self<<<NN * CIN / 256, 256>>>(x);
    k_wT<<<(CIN * CHID + CHID * CLAT) / 256 + 1, 256>>>(gw, lw);
    k_scatter<<<NE, 128>>>(x, ei);
    k_gcn<<<NN / 4, 256>>>(gb);
    k_z<<<NN / 4, 256>>>(batch, lb, z_node);
    k_graph<<<NG, 128>>>(dw, db, z_graph);
    k_xhat<<<NN * CIN / 256, 256>>>(batch, x_hat);

    dim3 grid(128, 128);
    k_ahat<<<grid, 256>>>(z_node, a_hat);
}

// round 5
// speedup vs baseline: 1.4099x; 1.4099x over previous
#include <cuda_runtime.h>
#include <cstdint>

#define NN   16384
#define NE   262144
#define NG   16
#define CIN  128
#define CHID 256
#define CLAT 64

// ---- scratch (device globals; no allocation allowed) ----
__device__ float g_deg[NN];
__device__ float g_dinv[NN];
__device__ float g_aggx[NN * CIN];    // aggregated x (pre-transform)
__device__ float g_h[NN * CHID];      // relu hidden
__device__ float g_wT[CIN * CHID];    // gcn_w transposed  [k][h]
__device__ float g_linT[CHID * CLAT]; // lin_w transposed  [k][c]
__device__ float g_zsum[NG * CLAT];
__device__ float g_cnt[NG];
__device__ float g_gdec[NG * CIN];

// packed f32x2 helpers (sm_100+)
__device__ __forceinline__ uint64_t pack2(float lo, float hi) {
    uint64_t p;
    asm("mov.b64 %0, {%1, %2};" : "=l"(p) : "f"(lo), "f"(hi));
    return p;
}
__device__ __forceinline__ void fma2(uint64_t& d, uint64_t a, uint64_t b) {
    asm("fma.rn.f32x2 %0, %1, %2, %0;" : "+l"(d) : "l"(a), "l"(b));
}
__device__ __forceinline__ void unpack2(uint64_t p, float& lo, float& hi) {
    asm("mov.b64 {%0, %1}, %2;" : "=f"(lo), "=f"(hi) : "l"(p));
}

// ---------------------------------------------------------
__global__ void k_init() {
    int i = blockIdx.x * blockDim.x + threadIdx.x;
    if (i < NN) g_deg[i] = 1.0f;          // self-loop
    if (i < NG * CLAT) g_zsum[i] = 0.0f;
    if (i < NG) g_cnt[i] = 0.0f;
}

__global__ void k_deg(const int* __restrict__ ei) {
    int e = blockIdx.x * blockDim.x + threadIdx.x;
    if (e < NE) atomicAdd(&g_deg[ei[NE + e]], 1.0f);
}

__global__ void k_dinv() {
    int i = blockIdx.x * blockDim.x + threadIdx.x;
    if (i < NN) g_dinv[i] = rsqrtf(g_deg[i]);
}

// self-loop term: aggx[i] = x[i] / deg[i]
__global__ void k_self(const float* __restrict__ x) {
    int idx = blockIdx.x * blockDim.x + threadIdx.x;
    if (idx < NN * CIN) g_aggx[idx] = x[idx] / g_deg[idx >> 7];
}

// edge scatter: one warp per edge, 4 channels/lane via red.global.add.v4.f32
__global__ void k_scatter(const float4* __restrict__ x4, const int* __restrict__ ei) {
    int gt = blockIdx.x * blockDim.x + threadIdx.x;
    int e = gt >> 5;
    int lane = gt & 31;
    if (e >= NE) return;
    int row = ei[e];
    int col = ei[NE + e];
    float norm = g_dinv[row] * g_dinv[col];
    float4 v = x4[row * 32 + lane];
    v.x *= norm; v.y *= norm; v.z *= norm; v.w *= norm;
    float* dst = &g_aggx[(col * 32 + lane) * 4];
    asm volatile("red.global.add.v4.f32 [%0], {%1, %2, %3, %4};"
                 :: "l"(dst), "f"(v.x), "f"(v.y), "f"(v.z), "f"(v.w) : "memory");
}

__global__ void k_wT(const float* __restrict__ gw, const float* __restrict__ lw) {
    int idx = blockIdx.x * blockDim.x + threadIdx.x;
    if (idx < CIN * CHID) {
        int h = idx >> 7, k = idx & 127;           // gcn_w [256][128]
        g_wT[k * CHID + h] = gw[idx];
    } else if (idx < CIN * CHID + CHID * CLAT) {
        int j = idx - CIN * CHID;
        int l = j >> 8, c = j & 255;               // lin_w [64][256]
        g_linT[c * CLAT + l] = lw[j];
    }
}

// h = relu(aggx @ gcn_w^T + gcn_b)   -- 4 nodes per block
__global__ void k_gcn(const float* __restrict__ gb) {
    __shared__ float sx[4][CIN];
    int i0 = blockIdx.x * 4;
    int t = threadIdx.x;
#pragma unroll
    for (int ii = 0; ii < 2; ii++) {
        int lin = t + ii * 256;
        sx[lin >> 7][lin & 127] = g_aggx[i0 * CIN + lin];
    }
    __syncthreads();
    float b = gb[t];
    float a0 = b, a1 = b, a2 = b, a3 = b;
#pragma unroll 4
    for (int k = 0; k < CIN; k++) {
        float w = g_wT[k * CHID + t];
        a0 += sx[0][k] * w;
        a1 += sx[1][k] * w;
        a2 += sx[2][k] * w;
        a3 += sx[3][k] * w;
    }
    g_h[(i0 + 0) * CHID + t] = fmaxf(a0, 0.f);
    g_h[(i0 + 1) * CHID + t] = fmaxf(a1, 0.f);
    g_h[(i0 + 2) * CHID + t] = fmaxf(a2, 0.f);
    g_h[(i0 + 3) * CHID + t] = fmaxf(a3, 0.f);
}

// z_node = h @ lin_w^T + lin_b  (+ graph pooling accumulation)
__global__ void k_z(const int* __restrict__ batch, const float* __restrict__ lb,
                    float* __restrict__ zout) {
    __shared__ float sA[4][CHID];
    int i0 = blockIdx.x * 4;
    int t = threadIdx.x;
#pragma unroll
    for (int ii = 0; ii < 4; ii++) {
        int lin = t + ii * 256;
        sA[lin >> 8][lin & 255] = g_h[i0 * CHID + lin];
    }
    __syncthreads();
    int j = t >> 6, c = t & 63;
    float acc = lb[c];
#pragma unroll 4
    for (int k = 0; k < CHID; k++) acc += sA[j][k] * g_linT[k * CLAT + c];
    int node = i0 + j;
    zout[node * CLAT + c] = acc;
    int b = batch[node];
    atomicAdd(&g_zsum[b * CLAT + c], acc);
    if (c == 0) atomicAdd(&g_cnt[b], 1.0f);
}

// z_graph + per-graph decoded row
__global__ void k_graph(const float* __restrict__ dw, const float* __restrict__ db,
                        float* __restrict__ zg_out) {
    __shared__ float zg[CLAT];
    int g = blockIdx.x, t = threadIdx.x;
    if (t < CLAT) {
        float cn = fmaxf(g_cnt[g], 1.0f);
        float v = g_zsum[g * CLAT + t] / cn;
        zg[t] = v;
        zg_out[g * CLAT + t] = v;
    }
    __syncthreads();
    float acc = db[t];
#pragma unroll
    for (int l = 0; l < CLAT; l++) acc += zg[l] * dw[t * CLAT + l];
    g_gdec[g * CIN + t] = acc;
}

__global__ void k_xhat(const int* __restrict__ batch, float* __restrict__ xo) {
    int idx = blockIdx.x * blockDim.x + threadIdx.x;
    if (idx < NN * CIN) {
        int i = idx >> 7;
        xo[idx] = g_gdec[batch[i] * CIN + (idx & 127)];
    }
}

// a_hat = sigmoid(Z Z^T), symmetric: compute upper-tri tiles, mirror via SMEM.
// Mainloop uses packed fma.rn.f32x2 (2 MACs/instr).
__global__ void __launch_bounds__(256) k_ahat(const float* __restrict__ Z,
                                              float* __restrict__ out) {
    __shared__ float sm[8704];           // 34816 bytes (fits both layouts)
    float* As = sm;                      // [32][132] chunk of A^T (As[k][m])
    float* Bs = sm + 32 * 132;           // [32][132]
    const int bi = blockIdx.y, bj = blockIdx.x;
    if (bj < bi) return;
    const int tid = threadIdx.x;
    const int m0 = bi * 128, n0 = bj * 128;
    const int ty = tid >> 4, tx = tid & 15;

    uint64_t cc[8][4];                   // packed accumulators: c[i][2j],c[i][2j+1]
#pragma unroll
    for (int a = 0; a < 8; a++)
#pragma unroll
        for (int b = 0; b < 4; b++) cc[a][b] = 0ull;

#pragma unroll
    for (int kk = 0; kk < 64; kk += 32) {
        // stage 128 rows x 32 k-values for A and B (transposed into smem)
#pragma unroll
        for (int i = 0; i < 4; i++) {
            int lin = tid + i * 256;       // 0..1023
            int row = lin >> 3;            // 0..127
            int kq  = (lin & 7) * 4;       // 0,4,...,28
            float4 va = *(const float4*)(Z + (m0 + row) * 64 + kk + kq);
            As[(kq + 0) * 132 + row] = va.x;
            As[(kq + 1) * 132 + row] = va.y;
            As[(kq + 2) * 132 + row] = va.z;
            As[(kq + 3) * 132 + row] = va.w;
            float4 vb = *(const float4*)(Z + (n0 + row) * 64 + kk + kq);
            Bs[(kq + 0) * 132 + row] = vb.x;
            Bs[(kq + 1) * 132 + row] = vb.y;
            Bs[(kq + 2) * 132 + row] = vb.z;
            Bs[(kq + 3) * 132 + row] = vb.w;
        }
        __syncthreads();
#pragma unroll 8
        for (int k = 0; k < 32; k++) {
            float4 a0 = *(const float4*)(As + k * 132 + ty * 8);
            float4 a1 = *(const float4*)(As + k * 132 + ty * 8 + 4);
            float4 b0 = *(const float4*)(Bs + k * 132 + tx * 8);
            float4 b1 = *(const float4*)(Bs + k * 132 + tx * 8 + 4);
            uint64_t bp[4];
            bp[0] = pack2(b0.x, b0.y);
            bp[1] = pack2(b0.z, b0.w);
            bp[2] = pack2(b1.x, b1.y);
            bp[3] = pack2(b1.z, b1.w);
            float ar[8] = {a0.x, a0.y, a0.z, a0.w, a1.x, a1.y, a1.z, a1.w};
#pragma unroll
            for (int ii = 0; ii < 8; ii++) {
                uint64_t ap = pack2(ar[ii], ar[ii]);
#pragma unroll
                for (int jj = 0; jj < 4; jj++) fma2(cc[ii][jj], ap, bp[jj]);
            }
        }
        __syncthreads();
    }

    float c[8][8];
#pragma unroll
    for (int ii = 0; ii < 8; ii++)
#pragma unroll
        for (int jj = 0; jj < 4; jj++)
            unpack2(cc[ii][jj], c[ii][jj * 2], c[ii][jj * 2 + 1]);

#pragma unroll
    for (int ii = 0; ii < 8; ii++)
#pragma unroll
        for (int jj = 0; jj < 8; jj++)
            c[ii][jj] = 1.0f / (1.0f + __expf(-c[ii][jj]));

    // direct tile (rows m0.., cols n0..), coalesced float4 stores
#pragma unroll
    for (int ii = 0; ii < 8; ii++) {
        long rowoff = (long)(m0 + ty * 8 + ii) * NN + n0 + tx * 8;
        *(float4*)(out + rowoff) = make_float4(c[ii][0], c[ii][1], c[ii][2], c[ii][3]);
        *(float4*)(out + rowoff + 4) = make_float4(c[ii][4], c[ii][5], c[ii][6], c[ii][7]);
    }
    if (bj == bi) return;

    // mirror tile: transpose via SMEM in two 64-column halves, float4 stores
    float* st = sm;  // [64][136] pitch 136 -> 16B-aligned rows
#pragma unroll
    for (int h = 0; h < 2; h++) {
        __syncthreads();
        if ((tx >> 3) == h) {
            int txl = tx & 7;  // 0..7 within half
#pragma unroll
            for (int jj = 0; jj < 8; jj++)
#pragma unroll
                for (int ii = 0; ii < 8; ii++)
                    st[(txl * 8 + jj) * 136 + ty * 8 + ii] = c[ii][jj];
        }
        __syncthreads();
#pragma unroll
        for (int p = 0; p < 8; p++) {
            int lin = p * 256 + tid;       // 0..2047
            int j = lin >> 5;              // 0..63
            int iq = lin & 31;             // 0..31 (float4 index)
            float4 v = *(const float4*)(st + j * 136 + iq * 4);
            *(float4*)(out + (long)(n0 + h * 64 + j) * NN + m0 + iq * 4) = v;
        }
    }
}

// ---------------------------------------------------------
extern "C" void kernel_launch(void* const* d_in, const int* in_sizes, int n_in,
                              void* d_out, int out_size) {
    const float* x     = (const float*)d_in[0];
    const int*   ei    = (const int*)d_in[1];
    const int*   batch = (const int*)d_in[2];
    const float* gw    = (const float*)d_in[3];
    const float* gb    = (const float*)d_in[4];
    const float* lw    = (const float*)d_in[5];
    const float* lb    = (const float*)d_in[6];
    const float* dw    = (const float*)d_in[7];
    const float* db    = (const float*)d_in[8];

    float* out     = (float*)d_out;
    float* z_node  = out;                       // [16384, 64]
    float* z_graph = out + NN * CLAT;           // [16, 64]
    float* x_hat   = z_graph + NG * CLAT;       // [16384, 128]
    float* a_hat   = x_hat + NN * CIN;          // [16384, 16384]

    k_init<<<64, 256>>>();
    k_deg<<<NE / 256, 256>>>(ei);
    k_dinv<<<NN / 256, 256>>>();
    k_self<<<NN * CIN / 256, 256>>>(x);
    k_wT<<<(CIN * CHID + CHID * CLAT) / 256 + 1, 256>>>(gw, lw);
    k_scatter<<<NE * 32 / 256, 256>>>((const float4*)x, ei);
    k_gcn<<<NN / 4, 256>>>(gb);
    k_z<<<NN / 4, 256>>>(batch, lb, z_node);
    k_graph<<<NG, 128>>>(dw, db, z_graph);
    k_xhat<<<NN * CIN / 256, 256>>>(batch, x_hat);

    dim3 grid(128, 128);
    k_ahat<<<grid, 256>>>(z_node, a_hat);
}